// round 1
// baseline (speedup 1.0000x reference)
#include <cuda_runtime.h>

#define TPB 256
#define MAX_BLOCKS 8192

__device__ float g_partials[MAX_BLOCKS];

__device__ __forceinline__ float compute_iou(float bx, float by, float bw, float bh,
                                             float lx, float ly, float lw, float lh) {
    const float invS = 1.0f / 7.0f;
    float x1 = bx * invS - bw * 0.5f;
    float y1 = by * invS - bh * 0.5f;
    float x2 = bx * invS + bw * 0.5f;
    float y2 = by * invS + bh * 0.5f;
    float u1 = lx * invS - lw * 0.5f;
    float v1 = ly * invS - lh * 0.5f;
    float u2 = lx * invS + lw * 0.5f;
    float v2 = ly * invS + lh * 0.5f;
    float a1 = (x2 - x1) * (y2 - y1);
    float a2 = (u2 - u1) * (v2 - v1);
    float left   = fmaxf(x1, u1);
    float right  = fminf(x2, u2);
    float top    = fmaxf(y1, v1);
    float bottom = fminf(y2, v2);
    bool valid = (left < right) && (top < bottom);
    float inter = valid ? (right - left) * (bottom - top) : 0.0f;
    float uni = a1 + a2 - inter;
    return valid ? (inter / uni) : 0.0f;
}

__global__ void yolo_cell_kernel(const float* __restrict__ predict,
                                 const float* __restrict__ label,
                                 int ncells) {
    int cell = blockIdx.x * blockDim.x + threadIdx.x;
    float loss = 0.0f;

    if (cell < ncells) {
        // Cheap always-needed scalars (96% of cells stop here)
        const float* pbase = predict + (size_t)cell * 26;
        const float* lbase = label   + (size_t)cell * 26;

        float l4 = __ldg(lbase + 4);
        float p4 = __ldg(pbase + 4);
        float p9 = __ldg(pbase + 9);

        // noobj confidence term (mask: conf_lab == 0)
        if (l4 == 0.0f) {
            loss = 0.5f * (p4 * p4 + p9 * p9);
        }

        // coord mask: conf_lab > 0 — full per-cell loss
        if (l4 > 0.0f) {
            float p[26], l[26];
            const float2* pp = reinterpret_cast<const float2*>(pbase);
            const float2* lp = reinterpret_cast<const float2*>(lbase);
#pragma unroll
            for (int j = 0; j < 13; j++) {
                float2 v = __ldg(pp + j);
                p[2 * j] = v.x; p[2 * j + 1] = v.y;
            }
#pragma unroll
            for (int j = 0; j < 13; j++) {
                float2 v = __ldg(lp + j);
                l[2 * j] = v.x; l[2 * j + 1] = v.y;
            }

            // class loss: sum over channels 10..25
            float class_loss = 0.0f;
#pragma unroll
            for (int j = 10; j < 26; j++) {
                float d = p[j] - l[j];
                class_loss += d * d;
            }

            float iou1 = compute_iou(p[0], p[1], p[2], p[3], l[0], l[1], l[2], l[3]);
            float iou2 = compute_iou(p[5], p[6], p[7], p[8], l[0], l[1], l[2], l[3]);
            bool pick1 = iou1 > iou2;

            float s0 = pick1 ? p[0] : p[5];
            float s1 = pick1 ? p[1] : p[6];
            float s2 = pick1 ? p[2] : p[7];
            float s3 = pick1 ? p[3] : p[8];

            float d0 = s0 - l[0];
            float d1 = s1 - l[1];
            float d2 = sqrtf(s2) - sqrtf(l[2]);
            float d3 = sqrtf(s3) - sqrtf(l[3]);
            float coord_cell = d0 * d0 + d1 * d1 + d2 * d2 + d3 * d3;

            float c  = pick1 ? p[4] : p[9];
            float io = pick1 ? iou1 : iou2;
            float dc = c - io;
            float obj_c_cell = dc * dc;

            float other = pick1 ? p[9] : p[4];
            float noobj_extra = other * other;

            loss += 5.0f * coord_cell + obj_c_cell + 0.5f * noobj_extra + class_loss;
        }
    }

    // ---- block reduction (shuffle within warps, then across warps) ----
    __shared__ float sm[TPB / 32];
    float s = loss;
#pragma unroll
    for (int o = 16; o > 0; o >>= 1)
        s += __shfl_down_sync(0xFFFFFFFFu, s, o);
    if ((threadIdx.x & 31) == 0)
        sm[threadIdx.x >> 5] = s;
    __syncthreads();
    if (threadIdx.x < 32) {
        s = (threadIdx.x < (TPB / 32)) ? sm[threadIdx.x] : 0.0f;
#pragma unroll
        for (int o = 16; o > 0; o >>= 1)
            s += __shfl_down_sync(0xFFFFFFFFu, s, o);
        if (threadIdx.x == 0)
            g_partials[blockIdx.x] = s;
    }
}

__global__ void yolo_reduce_kernel(float* __restrict__ out, int nblocks, float invN) {
    __shared__ float sm[32];
    float s = 0.0f;
    for (int i = threadIdx.x; i < nblocks; i += blockDim.x)
        s += g_partials[i];
#pragma unroll
    for (int o = 16; o > 0; o >>= 1)
        s += __shfl_down_sync(0xFFFFFFFFu, s, o);
    if ((threadIdx.x & 31) == 0)
        sm[threadIdx.x >> 5] = s;
    __syncthreads();
    if (threadIdx.x < 32) {
        s = (threadIdx.x < (int)(blockDim.x >> 5)) ? sm[threadIdx.x] : 0.0f;
#pragma unroll
        for (int o = 16; o > 0; o >>= 1)
            s += __shfl_down_sync(0xFFFFFFFFu, s, o);
        if (threadIdx.x == 0)
            out[0] = s * invN;
    }
}

extern "C" void kernel_launch(void* const* d_in, const int* in_sizes, int n_in,
                              void* d_out, int out_size) {
    const float* predict = (const float*)d_in[0];
    const float* label   = (const float*)d_in[1];
    float* out = (float*)d_out;

    int total  = in_sizes[0];          // B*7*7*26
    int ncells = total / 26;           // B*49
    int nblocks = (ncells + TPB - 1) / TPB;
    if (nblocks > MAX_BLOCKS) nblocks = MAX_BLOCKS;  // safety (never hit for this shape)

    float invN = 49.0f / (float)ncells;  // 1 / batch

    yolo_cell_kernel<<<nblocks, TPB>>>(predict, label, ncells);
    yolo_reduce_kernel<<<1, 1024>>>(out, nblocks, invN);
}